// round 1
// baseline (speedup 1.0000x reference)
#include <cuda_runtime.h>

#define MAXN 6016
#define NW   94      // ceil(6016/64)
#define D    8       // scan prefetch depth

// Scratch (device globals: allocation is banned)
__device__ float4             g_sboxes[MAXN];
__device__ float              g_sscores[MAXN];
__device__ int                g_sidx[MAXN];
__device__ unsigned long long g_mask[(size_t)MAXN * NW];  // zero-init; lower triangle stays 0
__device__ unsigned char      g_keep[MAXN];

// ---------------------------------------------------------------------------
// 1) Rank sort: rank[i] = #{j: s_j > s_i} + #{j<i: s_j == s_i}  (matches stable
//    argsort(-scores)). One warp per box; scatter box/score/idx to sorted pos.
// ---------------------------------------------------------------------------
__global__ void rank_kernel(const float* __restrict__ boxes,
                            const float* __restrict__ scores, int n) {
    int gw   = (blockIdx.x * blockDim.x + threadIdx.x) >> 5;
    int lane = threadIdx.x & 31;
    if (gw >= n) return;
    float s = scores[gw];
    int cnt = 0;
    for (int j = lane; j < n; j += 32) {
        float sj = scores[j];
        cnt += (int)((sj > s) | ((sj == s) & (j < gw)));
    }
    #pragma unroll
    for (int o = 16; o; o >>= 1) cnt += __shfl_down_sync(0xffffffffu, cnt, o);
    if (lane == 0) {
        const float4* b4 = (const float4*)boxes;
        g_sboxes[cnt]  = b4[gw];
        g_sscores[cnt] = s;
        g_sidx[cnt]    = gw;
    }
}

// ---------------------------------------------------------------------------
// 2) Suppression mask: bit k of g_mask[row][cb] set iff col=cb*64+k > row and
//    IoU(row,col) > 0.5 in sorted order. Lower-triangle words written to 0.
//    IEEE division to bit-match the XLA reference at the threshold boundary.
// ---------------------------------------------------------------------------
__global__ void mask_kernel(int n) {
    const int rb = blockIdx.y, cb = blockIdx.x;
    const int t  = threadIdx.x;          // 0..63
    const int row = rb * 64 + t;
    if (cb < rb) {                        // strictly lower triangle: zero it
        if (row < n) g_mask[(size_t)row * NW + cb] = 0ULL;
        return;
    }
    __shared__ float4 cbox[64];
    const int col0 = cb * 64;
    cbox[t] = (col0 + t < n) ? g_sboxes[col0 + t]
                             : make_float4(0.f, 0.f, 0.f, 0.f);  // degenerate -> IoU 0
    __syncthreads();
    if (row >= n) return;

    float4 b = g_sboxes[row];
    float area = (b.z - b.x) * (b.w - b.y);
    unsigned long long bits = 0ULL;
    #pragma unroll
    for (int k = 0; k < 64; k++) {
        int col = col0 + k;
        if (col > row) {
            float4 c = cbox[k];
            float iw = fmaxf(fminf(b.z, c.z) - fmaxf(b.x, c.x), 0.f);
            float ih = fmaxf(fminf(b.w, c.w) - fmaxf(b.y, c.y), 0.f);
            float inter = iw * ih;
            float ca  = (c.z - c.x) * (c.w - c.y);
            float uni = (area + ca) - inter;
            if (__fdiv_rn(inter, uni) > 0.5f) bits |= (1ULL << k);
        }
    }
    g_mask[(size_t)row * NW + cb] = bits;
}

// ---------------------------------------------------------------------------
// 3) Greedy serial scan: single warp. 94-word suppression bitmap lives in
//    registers (lane l owns words l, l+32, l+64). Bit test = 1 SHFL of the
//    owning lane's word. Update is branchless: m = bit-1 (all-ones iff kept).
//    Mask rows prefetched D deep unconditionally (loads never on the chain).
// ---------------------------------------------------------------------------
__global__ void scan_kernel(int n) {
    const int lane = threadIdx.x;
    unsigned long long r0 = 0ULL, r1 = 0ULL, r2 = 0ULL;
    const int w0 = lane, w1 = lane + 32, w2 = lane + 64;
    const bool v2 = (w2 < NW);

    unsigned long long buf0[D], buf1[D], buf2[D];
    #pragma unroll
    for (int p = 0; p < D; p++) {
        bool ok = (p < n);
        const unsigned long long* row = g_mask + (size_t)p * NW;
        buf0[p] = ok ? row[w0] : 0ULL;
        buf1[p] = ok ? row[w1] : 0ULL;
        buf2[p] = (ok && v2) ? row[w2] : 0ULL;
    }

    for (int base = 0; base < n; base += D) {
        #pragma unroll
        for (int p = 0; p < D; p++) {
            const int i = base + p;
            if (i >= n) return;
            const int wi = i >> 6;  // uniform across warp
            unsigned long long sel = (wi < 32) ? r0 : ((wi < 64) ? r1 : r2);
            unsigned long long rw  = __shfl_sync(0xffffffffu, sel, wi & 31);
            unsigned long long bit = (rw >> (i & 63)) & 1ULL;
            unsigned long long m   = bit - 1ULL;     // kept -> ~0, suppressed -> 0
            r0 |= buf0[p] & m;
            r1 |= buf1[p] & m;
            r2 |= buf2[p] & m;
            if (lane == 0) g_keep[i] = (unsigned char)(m & 1ULL);
            const int nr = i + D;
            if (nr < n) {
                const unsigned long long* row = g_mask + (size_t)nr * NW;
                buf0[p] = row[w0];
                buf1[p] = row[w1];
                buf2[p] = v2 ? row[w2] : 0ULL;
            }
        }
    }
}

// ---------------------------------------------------------------------------
// 4) Finalize: out[orig_idx] = score if (kept && score >= 0.6) else 0.
//    Every output element written exactly once (rank is a permutation).
// ---------------------------------------------------------------------------
__global__ void finalize_kernel(float* __restrict__ out, int n) {
    int i = blockIdx.x * blockDim.x + threadIdx.x;
    if (i >= n) return;
    float s = g_sscores[i];
    float v = (g_keep[i] && (s >= 0.6f)) ? s : 0.0f;
    out[g_sidx[i]] = v;
}

// ---------------------------------------------------------------------------
extern "C" void kernel_launch(void* const* d_in, const int* in_sizes, int n_in,
                              void* d_out, int out_size) {
    const float* boxes  = (const float*)d_in[0];
    const float* scores = (const float*)d_in[1];
    const int n = in_sizes[1];                 // 6000

    rank_kernel<<<(n * 32 + 255) / 256, 256>>>(boxes, scores, n);

    const int nb = (n + 63) / 64;              // 94
    dim3 grid(nb, nb);
    mask_kernel<<<grid, 64>>>(n);

    scan_kernel<<<1, 32>>>(n);

    finalize_kernel<<<(n + 255) / 256, 256>>>((float*)d_out, n);
}

// round 2
// speedup vs baseline: 1.2500x; 1.2500x over previous
#include <cuda_runtime.h>

#define MAXN 6016
#define NW   94      // ceil(6016/64) mask words per row
#define NB   94      // number of 64-box blocks

// Scratch (device globals: allocation is banned)
__device__ float4             g_sboxes[MAXN];
__device__ float              g_sscores[MAXN];
__device__ int                g_sidx[MAXN];
__device__ unsigned long long g_mask[(size_t)MAXN * NW];  // upper triangle only (rows >= n stay 0)
__device__ unsigned long long g_keepw[NB];

// ---------------------------------------------------------------------------
// 1) Rank sort: rank[i] = #{j: s_j > s_i} + #{j<i: s_j == s_i}  (stable
//    argsort(-scores)). One warp per box; scatter box/score/idx to sorted pos.
// ---------------------------------------------------------------------------
__global__ void rank_kernel(const float* __restrict__ boxes,
                            const float* __restrict__ scores, int n) {
    int gw   = (blockIdx.x * blockDim.x + threadIdx.x) >> 5;
    int lane = threadIdx.x & 31;
    if (gw >= n) return;
    float s = scores[gw];
    int cnt = 0;
    for (int j = lane; j < n; j += 32) {
        float sj = scores[j];
        cnt += (int)((sj > s) | ((sj == s) & (j < gw)));
    }
    #pragma unroll
    for (int o = 16; o; o >>= 1) cnt += __shfl_down_sync(0xffffffffu, cnt, o);
    if (lane == 0) {
        const float4* b4 = (const float4*)boxes;
        g_sboxes[cnt]  = b4[gw];
        g_sscores[cnt] = s;
        g_sidx[cnt]    = gw;
    }
}

// ---------------------------------------------------------------------------
// 2) Suppression mask (upper triangle + diagonal blocks only): bit k of
//    g_mask[row][cb] set iff col=cb*64+k > row and IoU(row,col) > 0.5.
//    IEEE division to bit-match the XLA reference at the threshold boundary.
// ---------------------------------------------------------------------------
__global__ void mask_kernel(int n) {
    const int rb = blockIdx.y, cb = blockIdx.x;
    if (cb < rb) return;                  // lower triangle never read
    const int t  = threadIdx.x;           // 0..63
    const int row = rb * 64 + t;
    __shared__ float4 cbox[64];
    const int col0 = cb * 64;
    cbox[t] = (col0 + t < n) ? g_sboxes[col0 + t]
                             : make_float4(0.f, 0.f, 0.f, 0.f);  // degenerate -> IoU 0
    __syncthreads();
    if (row >= n) return;

    float4 b = g_sboxes[row];
    float area = (b.z - b.x) * (b.w - b.y);
    unsigned long long bits = 0ULL;
    #pragma unroll
    for (int k = 0; k < 64; k++) {
        int col = col0 + k;
        if (col > row) {
            float4 c = cbox[k];
            float iw = fmaxf(fminf(b.z, c.z) - fmaxf(b.x, c.x), 0.f);
            float ih = fmaxf(fminf(b.w, c.w) - fmaxf(b.y, c.y), 0.f);
            float inter = iw * ih;
            float ca  = (c.z - c.x) * (c.w - c.y);
            float uni = (area + ca) - inter;
            if (__fdiv_rn(inter, uni) > 0.5f) bits |= (1ULL << k);
        }
    }
    g_mask[(size_t)row * NW + cb] = bits;
}

// ---------------------------------------------------------------------------
// 3) Greedy scan, block-sparse form. One CTA, 160 threads:
//      thread 0        : serial resolve of block b using diag words (visits
//                        only rows with nonzero diag -> ~popc(nz) steps)
//      threads 1..93   : per-word owners, OR kept rows' mask words into remv
//      threads 96..159 : prefetch next block's 64 diagonal words + nz ballot
//    No atomics, no shuffles on the serial chain.
// ---------------------------------------------------------------------------
__global__ void scan_kernel(int n) {
    __shared__ unsigned long long remv[NB];
    __shared__ unsigned long long diag[2][64];
    __shared__ unsigned int       nzp[2][2];
    __shared__ unsigned long long keptw_s;
    const int t = threadIdx.x;
    const int lrow = t - 96;   // loader row, 0..63 for loader threads

    if (t < NB) remv[t] = 0ULL;

    // Prefetch block 0 diagonal
    if (lrow >= 0) {
        unsigned long long d = (lrow < n) ? g_mask[(size_t)lrow * NW + 0] : 0ULL;
        diag[0][lrow] = d;
        unsigned bal = __ballot_sync(0xffffffffu, d != 0ULL);
        if ((t & 31) == 0) nzp[0][lrow >> 5] = bal;
    }
    __syncthreads();

    for (int b = 0; b < NB; b++) {
        const int cur = b & 1;

        if (lrow >= 0) {
            // Loaders: prefetch diag of block b+1 (runs concurrently w/ resolve)
            const int nb2 = b + 1;
            if (nb2 < NB) {
                const int row = nb2 * 64 + lrow;
                unsigned long long d = (row < n)
                    ? g_mask[(size_t)row * NW + nb2] : 0ULL;
                diag[cur ^ 1][lrow] = d;
                unsigned bal = __ballot_sync(0xffffffffu, d != 0ULL);
                if ((t & 31) == 0) nzp[cur ^ 1][lrow >> 5] = bal;
            }
        } else if (t == 0) {
            // Serial resolve: only visit rows with intra-block conflicts
            unsigned long long supp = remv[b];
            unsigned long long rem  = (unsigned long long)nzp[cur][0]
                                    | ((unsigned long long)nzp[cur][1] << 32);
            rem &= ~supp;
            while (rem) {
                const int i = __ffsll((long long)rem) - 1;
                rem &= rem - 1ULL;
                if (!((supp >> i) & 1ULL)) {
                    supp |= diag[cur][i];
                    rem  &= ~supp;       // skip rows we just suppressed
                }
            }
            const int vr = n - b * 64;
            const unsigned long long valid =
                (vr >= 64) ? ~0ULL : ((vr <= 0) ? 0ULL : ((1ULL << vr) - 1ULL));
            const unsigned long long kept = ~supp & valid;
            keptw_s   = kept;
            g_keepw[b] = kept;
        }
        __syncthreads();

        // Owners: accumulate kept rows' suppression into future words
        if (t > b && t < NB) {
            const unsigned long long kept = keptw_s;
            const unsigned long long* base = g_mask + (size_t)(b * 64) * NW + t;
            unsigned long long acc = 0ULL;
            #pragma unroll 8
            for (int i = 0; i < 64; i++) {
                unsigned long long m = 0ULL - ((kept >> i) & 1ULL);
                acc |= base[(size_t)i * NW] & m;
            }
            remv[t] |= acc;
        }
        __syncthreads();
    }
}

// ---------------------------------------------------------------------------
// 4) Finalize: out[orig_idx] = score if (kept && score >= 0.6) else 0.
// ---------------------------------------------------------------------------
__global__ void finalize_kernel(float* __restrict__ out, int n) {
    int i = blockIdx.x * blockDim.x + threadIdx.x;
    if (i >= n) return;
    float s = g_sscores[i];
    int kb = (int)((g_keepw[i >> 6] >> (i & 63)) & 1ULL);
    out[g_sidx[i]] = (kb && (s >= 0.6f)) ? s : 0.0f;
}

// ---------------------------------------------------------------------------
extern "C" void kernel_launch(void* const* d_in, const int* in_sizes, int n_in,
                              void* d_out, int out_size) {
    const float* boxes  = (const float*)d_in[0];
    const float* scores = (const float*)d_in[1];
    const int n = in_sizes[1];                 // 6000

    rank_kernel<<<(n * 32 + 255) / 256, 256>>>(boxes, scores, n);

    dim3 grid(NB, NB);
    mask_kernel<<<grid, 64>>>(n);

    scan_kernel<<<1, 160>>>(n);

    finalize_kernel<<<(n + 255) / 256, 256>>>((float*)d_out, n);
}

// round 3
// speedup vs baseline: 3.3538x; 2.6831x over previous
#include <cuda_runtime.h>

#define MAXN 6016
#define NW   94      // ceil(6016/64) mask words per row
#define NB   94      // number of 64-box blocks (worst case)

// Scratch (device globals: allocation is banned; zero-initialized at load)
__device__ float4             g_sboxes[MAXN];
__device__ float              g_sscores[MAXN];
__device__ int                g_sidx[MAXN];
__device__ unsigned long long g_mask[(size_t)MAXN * NW];
__device__ unsigned long long g_keepw[NB];
__device__ int                g_m;    // #{scores >= 0.6}
__device__ int                g_mb;   // ceil(g_m / 64)

// ---------------------------------------------------------------------------
// 0) Count confidence prefix: m = #{s >= 0.6}. Only the top-m (sorted) boxes
//    can influence the output, so mask/scan work shrinks to the prefix.
// ---------------------------------------------------------------------------
__global__ void count_kernel(const float* __restrict__ scores, int n) {
    __shared__ int red[32];
    const int t = threadIdx.x;
    int c = 0;
    for (int i = t; i < n; i += 1024) c += (scores[i] >= 0.6f);
    #pragma unroll
    for (int o = 16; o; o >>= 1) c += __shfl_down_sync(0xffffffffu, c, o);
    if ((t & 31) == 0) red[t >> 5] = c;
    __syncthreads();
    if (t < 32) {
        int v = red[t];
        #pragma unroll
        for (int o = 16; o; o >>= 1) v += __shfl_down_sync(0xffffffffu, v, o);
        if (t == 0) { g_m = v; g_mb = (v + 63) >> 6; }
    }
}

// ---------------------------------------------------------------------------
// 1) Rank sort: rank[i] = #{j: s_j > s_i} + #{j<i: s_j == s_i}  (stable
//    argsort(-scores)). One warp per box; scatter box/score/idx to sorted pos.
// ---------------------------------------------------------------------------
__global__ void rank_kernel(const float* __restrict__ boxes,
                            const float* __restrict__ scores, int n) {
    int gw   = (blockIdx.x * blockDim.x + threadIdx.x) >> 5;
    int lane = threadIdx.x & 31;
    if (gw >= n) return;
    float s = scores[gw];
    int cnt = 0;
    for (int j = lane; j < n; j += 32) {
        float sj = scores[j];
        cnt += (int)((sj > s) | ((sj == s) & (j < gw)));
    }
    #pragma unroll
    for (int o = 16; o; o >>= 1) cnt += __shfl_down_sync(0xffffffffu, cnt, o);
    if (lane == 0) {
        const float4* b4 = (const float4*)boxes;
        g_sboxes[cnt]  = b4[gw];
        g_sscores[cnt] = s;
        g_sidx[cnt]    = gw;
    }
}

// ---------------------------------------------------------------------------
// 2) Suppression mask on the confidence prefix only. bit k of g_mask[row][cb]
//    set iff col=cb*64+k > row and IoU > 0.5. Division-free exact test:
//    iou > 0.5  <=>  fma(-0.5, uni, inter) > 0  (0.5*uni exact; FMA single
//    rounding preserves sign; exact tie -> both sides say "no").
// ---------------------------------------------------------------------------
__global__ void mask_kernel(int n) {
    const int mb = g_mb;
    const int rb = blockIdx.y, cb = blockIdx.x;
    if (cb < rb || rb >= mb || cb >= mb) return;
    const int t = threadIdx.x;                   // 0..63
    const int m_pad = min(n, mb * 64);

    __shared__ float4 cbox[64];                  // {cz, cw, -cx, -cy}
    __shared__ float  carea[64];
    const int col0 = cb * 64;
    if (col0 + t < m_pad) {
        float4 c = g_sboxes[col0 + t];
        cbox[t]  = make_float4(c.z, c.w, -c.x, -c.y);
        carea[t] = (c.z - c.x) * (c.w - c.y);
    } else {
        cbox[t]  = make_float4(-1e30f, -1e30f, -1e30f, -1e30f);  // -> IoU 0
        carea[t] = 0.f;
    }
    __syncthreads();

    const int row = rb * 64 + t;
    if (row >= m_pad) return;

    const float4 b   = g_sboxes[row];
    const float  bz  = b.z,  bw  = b.w;
    const float  nbx = -b.x, nby = -b.y;
    const float  barea = (b.z - b.x) * (b.w - b.y);

    unsigned long long bits = 0ULL;
    #pragma unroll
    for (int k = 0; k < 64; k++) {
        float4 c  = cbox[k];
        float iw  = fmaxf(fminf(bz, c.x) + fminf(nbx, c.z), 0.f);  // min(x2)-max(x1)
        float ih  = fmaxf(fminf(bw, c.y) + fminf(nby, c.w), 0.f);
        float inter = iw * ih;
        float uni   = (barea + carea[k]) - inter;
        if (fmaf(-0.5f, uni, inter) > 0.f) bits |= (1ULL << k);
    }
    if (cb == rb) bits &= ((~1ULL) << t);        // keep only cols > row
    g_mask[(size_t)row * NW + cb] = bits;
}

// ---------------------------------------------------------------------------
// 3) Greedy scan, block-sparse. One CTA, 160 threads:
//      thread 0      : serial resolve of block b (visits only conflict rows)
//      threads 1..93 : per-word owners, OR kept rows' mask words into remv
//      threads 96..159: prefetch next block's diagonal + nonzero ballot
// ---------------------------------------------------------------------------
__global__ void scan_kernel(int n) {
    __shared__ unsigned long long remv[NB];
    __shared__ unsigned long long diag[2][64];
    __shared__ unsigned int       nzp[2][2];
    __shared__ unsigned long long keptw_s;
    const int t = threadIdx.x;
    const int lrow = t - 96;
    const int mb = g_mb;
    const int m_pad = min(n, mb * 64);

    if (t < NB) remv[t] = 0ULL;

    if (lrow >= 0) {
        unsigned long long d = (lrow < m_pad && mb > 0)
            ? g_mask[(size_t)lrow * NW + 0] : 0ULL;
        diag[0][lrow] = d;
        unsigned bal = __ballot_sync(0xffffffffu, d != 0ULL);
        if ((t & 31) == 0) nzp[0][lrow >> 5] = bal;
    }
    __syncthreads();

    for (int b = 0; b < mb; b++) {
        const int cur = b & 1;

        if (lrow >= 0) {
            const int nb2 = b + 1;
            if (nb2 < mb) {
                const int row = nb2 * 64 + lrow;
                unsigned long long d = (row < m_pad)
                    ? g_mask[(size_t)row * NW + nb2] : 0ULL;
                diag[cur ^ 1][lrow] = d;
                unsigned bal = __ballot_sync(0xffffffffu, d != 0ULL);
                if ((t & 31) == 0) nzp[cur ^ 1][lrow >> 5] = bal;
            }
        } else if (t == 0) {
            unsigned long long supp = remv[b];
            unsigned long long rem  = (unsigned long long)nzp[cur][0]
                                    | ((unsigned long long)nzp[cur][1] << 32);
            rem &= ~supp;
            while (rem) {
                const int i = __ffsll((long long)rem) - 1;
                rem &= rem - 1ULL;
                if (!((supp >> i) & 1ULL)) {
                    supp |= diag[cur][i];
                    rem  &= ~supp;
                }
            }
            const int vr = m_pad - b * 64;
            const unsigned long long valid =
                (vr >= 64) ? ~0ULL : ((vr <= 0) ? 0ULL : ((1ULL << vr) - 1ULL));
            const unsigned long long kept = ~supp & valid;
            keptw_s    = kept;
            g_keepw[b] = kept;
        }
        __syncthreads();

        if (t > b && t < mb) {
            const unsigned long long kept = keptw_s;
            const unsigned long long* base = g_mask + (size_t)(b * 64) * NW + t;
            unsigned long long acc = 0ULL;
            #pragma unroll 8
            for (int i = 0; i < 64; i++) {
                unsigned long long m = 0ULL - ((kept >> i) & 1ULL);
                acc |= base[(size_t)i * NW] & m;
            }
            remv[t] |= acc;
        }
        __syncthreads();
    }
}

// ---------------------------------------------------------------------------
// 4) Finalize: out[orig_idx] = score if (kept && score >= 0.6) else 0.
//    Blocks >= g_mb were never written; zero-init -> kept=0, and s<0.6 anyway.
// ---------------------------------------------------------------------------
__global__ void finalize_kernel(float* __restrict__ out, int n) {
    int i = blockIdx.x * blockDim.x + threadIdx.x;
    if (i >= n) return;
    float s = g_sscores[i];
    int kb = (int)((g_keepw[i >> 6] >> (i & 63)) & 1ULL);
    out[g_sidx[i]] = (kb && (s >= 0.6f)) ? s : 0.0f;
}

// ---------------------------------------------------------------------------
extern "C" void kernel_launch(void* const* d_in, const int* in_sizes, int n_in,
                              void* d_out, int out_size) {
    const float* boxes  = (const float*)d_in[0];
    const float* scores = (const float*)d_in[1];
    const int n = in_sizes[1];                 // 6000

    count_kernel<<<1, 1024>>>(scores, n);
    rank_kernel<<<(n * 32 + 255) / 256, 256>>>(boxes, scores, n);

    dim3 grid(NB, NB);
    mask_kernel<<<grid, 64>>>(n);

    scan_kernel<<<1, 160>>>(n);

    finalize_kernel<<<(n + 255) / 256, 256>>>((float*)d_out, n);
}

// round 4
// speedup vs baseline: 12.0055x; 3.5796x over previous
#include <cuda_runtime.h>

#define MAXN 6016
#define NW   94      // ceil(6016/64) mask words per row
#define NB   94      // number of 64-box blocks (worst case)

typedef unsigned long long u64;

// Scratch (device globals: allocation is banned; zero-initialized at load)
__device__ float4 g_sboxes[MAXN];
__device__ float  g_sscores[MAXN];
__device__ int    g_sidx[MAXN];
__device__ u64    g_maskT[(size_t)NW * MAXN];   // TRANSPOSED: [word][row]
__device__ u64    g_keepw[NB];
__device__ int    g_m;    // #{scores >= 0.6}
__device__ int    g_mb;   // ceil(g_m / 64)

// ---------------------------------------------------------------------------
// 0) Count confidence prefix: m = #{s >= 0.6}.
// ---------------------------------------------------------------------------
__global__ void count_kernel(const float* __restrict__ scores, int n) {
    __shared__ int red[32];
    const int t = threadIdx.x;
    int c = 0;
    for (int i = t; i < n; i += 1024) c += (scores[i] >= 0.6f);
    #pragma unroll
    for (int o = 16; o; o >>= 1) c += __shfl_down_sync(0xffffffffu, c, o);
    if ((t & 31) == 0) red[t >> 5] = c;
    __syncthreads();
    if (t < 32) {
        int v = red[t];
        #pragma unroll
        for (int o = 16; o; o >>= 1) v += __shfl_down_sync(0xffffffffu, v, o);
        if (t == 0) { g_m = v; g_mb = (v + 63) >> 6; }
    }
}

// ---------------------------------------------------------------------------
// 1) Rank sort (stable argsort(-scores)): one warp per box, scatter to rank.
// ---------------------------------------------------------------------------
__global__ void rank_kernel(const float* __restrict__ boxes,
                            const float* __restrict__ scores, int n) {
    int gw   = (blockIdx.x * blockDim.x + threadIdx.x) >> 5;
    int lane = threadIdx.x & 31;
    if (gw >= n) return;
    float s = scores[gw];
    int cnt = 0;
    for (int j = lane; j < n; j += 32) {
        float sj = scores[j];
        cnt += (int)((sj > s) | ((sj == s) & (j < gw)));
    }
    #pragma unroll
    for (int o = 16; o; o >>= 1) cnt += __shfl_down_sync(0xffffffffu, cnt, o);
    if (lane == 0) {
        const float4* b4 = (const float4*)boxes;
        g_sboxes[cnt]  = b4[gw];
        g_sscores[cnt] = s;
        g_sidx[cnt]    = gw;
    }
}

// ---------------------------------------------------------------------------
// 2) Suppression mask on the prefix, TRANSPOSED output: g_maskT[cb][row].
//    Division-free exact threshold: iou>0.5 <=> fma(-0.5,uni,inter)>0.
// ---------------------------------------------------------------------------
__global__ void mask_kernel(int n) {
    const int mb = g_mb;
    const int rb = blockIdx.y, cb = blockIdx.x;
    if (cb < rb || rb >= mb || cb >= mb) return;
    const int t = threadIdx.x;                   // 0..63
    const int m_pad = min(n, mb * 64);

    __shared__ float4 cbox[64];                  // {cz, cw, -cx, -cy}
    __shared__ float  carea[64];
    const int col0 = cb * 64;
    if (col0 + t < m_pad) {
        float4 c = g_sboxes[col0 + t];
        cbox[t]  = make_float4(c.z, c.w, -c.x, -c.y);
        carea[t] = (c.z - c.x) * (c.w - c.y);
    } else {
        cbox[t]  = make_float4(-1e30f, -1e30f, -1e30f, -1e30f);  // -> IoU 0
        carea[t] = 0.f;
    }
    __syncthreads();

    const int row = rb * 64 + t;
    if (row >= m_pad) return;

    const float4 b   = g_sboxes[row];
    const float  bz  = b.z,  bw  = b.w;
    const float  nbx = -b.x, nby = -b.y;
    const float  barea = (b.z - b.x) * (b.w - b.y);

    u64 bits = 0ULL;
    #pragma unroll
    for (int k = 0; k < 64; k++) {
        float4 c  = cbox[k];
        float iw  = fmaxf(fminf(bz, c.x) + fminf(nbx, c.z), 0.f);  // min(x2)-max(x1)
        float ih  = fmaxf(fminf(bw, c.y) + fminf(nby, c.w), 0.f);
        float inter = iw * ih;
        float uni   = (barea + carea[k]) - inter;
        if (fmaf(-0.5f, uni, inter) > 0.f) bits |= (1ULL << k);
    }
    if (cb == rb) bits &= ((~1ULL) << t);        // keep only cols > row
    g_maskT[(size_t)cb * MAXN + row] = bits;     // coalesced across t
}

// ---------------------------------------------------------------------------
// 3) Greedy scan, 1024 threads:
//      thread 0  : serial resolve of block b (visits only conflict rows)
//      warp 31   : double-buffered prefetch of next diagonal + nz bitmap
//      all warps : sweep — warp w OR-reduces column word j=b+1+w(+32) over the
//                  64 kept rows (2 contiguous loads/lane + shfl_xor reduce)
// ---------------------------------------------------------------------------
__global__ void scan_kernel(int n) {
    __shared__ u64 remv[NB];
    __shared__ u64 diag[2][64];
    __shared__ u64 nzw[2];
    __shared__ u64 keptw_s;
    const int t = threadIdx.x;
    const int warp = t >> 5, lane = t & 31;
    const int mb = g_mb;
    const int m_pad = min(n, mb * 64);

    if (t < NB) remv[t] = 0ULL;

    if (warp == 31 && mb > 0) {                  // prefetch diag block 0
        u64 d0 = (lane      < m_pad) ? g_maskT[lane]      : 0ULL;
        u64 d1 = (lane + 32 < m_pad) ? g_maskT[lane + 32] : 0ULL;
        diag[0][lane]      = d0;
        diag[0][lane + 32] = d1;
        unsigned b0 = __ballot_sync(0xffffffffu, d0 != 0ULL);
        unsigned b1 = __ballot_sync(0xffffffffu, d1 != 0ULL);
        if (lane == 0) nzw[0] = (u64)b0 | ((u64)b1 << 32);
    }
    __syncthreads();

    for (int b = 0; b < mb; b++) {
        const int cur = b & 1;

        if (warp == 31) {
            const int nb2 = b + 1;
            if (nb2 < mb) {                      // prefetch next diagonal
                const u64* col = g_maskT + (size_t)nb2 * MAXN + nb2 * 64;
                u64 d0 = (nb2 * 64 + lane      < m_pad) ? col[lane]      : 0ULL;
                u64 d1 = (nb2 * 64 + lane + 32 < m_pad) ? col[lane + 32] : 0ULL;
                diag[cur ^ 1][lane]      = d0;
                diag[cur ^ 1][lane + 32] = d1;
                unsigned b0 = __ballot_sync(0xffffffffu, d0 != 0ULL);
                unsigned b1 = __ballot_sync(0xffffffffu, d1 != 0ULL);
                if (lane == 0) nzw[cur ^ 1] = (u64)b0 | ((u64)b1 << 32);
            }
        } else if (t == 0) {                     // serial resolve
            u64 supp = remv[b];
            u64 rem  = nzw[cur] & ~supp;
            while (rem) {
                const int i = __ffsll((long long)rem) - 1;
                rem &= rem - 1ULL;
                if (!((supp >> i) & 1ULL)) {
                    supp |= diag[cur][i];
                    rem  &= ~supp;
                }
            }
            const int vr = m_pad - b * 64;
            const u64 valid = (vr >= 64) ? ~0ULL
                             : ((vr <= 0) ? 0ULL : ((1ULL << vr) - 1ULL));
            const u64 kept = ~supp & valid;
            keptw_s    = kept;
            g_keepw[b] = kept;
        }
        __syncthreads();

        // Parallel sweep: accumulate kept rows' suppression into future words
        const u64 kept = keptw_s;
        for (int j = b + 1 + warp; j < mb; j += 32) {
            const u64* col = g_maskT + (size_t)j * MAXN + b * 64;
            u64 d0 = col[lane]      & (0ULL - ((kept >> lane)        & 1ULL));
            u64 d1 = col[lane + 32] & (0ULL - ((kept >> (lane + 32)) & 1ULL));
            u64 acc = d0 | d1;
            #pragma unroll
            for (int o = 16; o; o >>= 1)
                acc |= __shfl_xor_sync(0xffffffffu, acc, o);
            if (lane == 0) remv[j] |= acc;
        }
        __syncthreads();
    }
}

// ---------------------------------------------------------------------------
// 4) Finalize: out[orig_idx] = score if (kept && score >= 0.6) else 0.
// ---------------------------------------------------------------------------
__global__ void finalize_kernel(float* __restrict__ out, int n) {
    int i = blockIdx.x * blockDim.x + threadIdx.x;
    if (i >= n) return;
    float s = g_sscores[i];
    int kb = (int)((g_keepw[i >> 6] >> (i & 63)) & 1ULL);
    out[g_sidx[i]] = (kb && (s >= 0.6f)) ? s : 0.0f;
}

// ---------------------------------------------------------------------------
extern "C" void kernel_launch(void* const* d_in, const int* in_sizes, int n_in,
                              void* d_out, int out_size) {
    const float* boxes  = (const float*)d_in[0];
    const float* scores = (const float*)d_in[1];
    const int n = in_sizes[1];                 // 6000

    count_kernel<<<1, 1024>>>(scores, n);
    rank_kernel<<<(n * 32 + 255) / 256, 256>>>(boxes, scores, n);

    dim3 grid(NB, NB);
    mask_kernel<<<grid, 64>>>(n);

    scan_kernel<<<1, 1024>>>(n);

    finalize_kernel<<<(n + 255) / 256, 256>>>((float*)d_out, n);
}

// round 5
// speedup vs baseline: 14.5288x; 1.2102x over previous
#include <cuda_runtime.h>

#define MAXN 6016
#define NB   94      // max number of 64-box blocks
#define SWEEP_WARPS 30
#define MAXJ 4       // ceil((NB-1)/SWEEP_WARPS)

typedef unsigned long long u64;

// Scratch (device globals: allocation is banned; zero-initialized at load)
__device__ float4 g_sboxes[MAXN];
__device__ int    g_rank[MAXN];
__device__ u64    g_maskT[(size_t)NB * MAXN];   // TRANSPOSED: [word][row]
__device__ u64    g_keepw[NB];
__device__ int    g_m;    // #{scores >= 0.6}; atomicMax (idempotent across replays)

// ---------------------------------------------------------------------------
// 1) Rank of prefix boxes (s >= 0.6). Suffix boxes can neither appear in the
//    output nor suppress a prefix box (suppression flows high->low score), so
//    their warps exit immediately. Prefix ranks are exactly 0..m-1; m is
//    published via idempotent atomicMax.
// ---------------------------------------------------------------------------
__global__ void rank_kernel(const float* __restrict__ boxes,
                            const float* __restrict__ scores, int n) {
    int gw   = (blockIdx.x * blockDim.x + threadIdx.x) >> 5;
    int lane = threadIdx.x & 31;
    if (gw >= n) return;
    float s = scores[gw];
    if (s < 0.6f) return;                        // irrelevant to output
    int cnt = 0;
    for (int j = lane; j < n; j += 32) {
        float sj = scores[j];
        cnt += (int)((sj > s) | ((sj == s) & (j < gw)));
    }
    #pragma unroll
    for (int o = 16; o; o >>= 1) cnt += __shfl_down_sync(0xffffffffu, cnt, o);
    if (lane == 0) {
        const float4* b4 = (const float4*)boxes;
        g_sboxes[cnt] = b4[gw];
        g_rank[gw]    = cnt;
        atomicMax(&g_m, cnt + 1);
    }
}

// ---------------------------------------------------------------------------
// 2) Suppression mask on the prefix, TRANSPOSED output: g_maskT[cb][row].
//    Division-free exact threshold: iou>0.5 <=> fma(-0.5,uni,inter)>0.
// ---------------------------------------------------------------------------
__global__ void mask_kernel(int n) {
    int m = g_m; if (m > n) m = n;
    const int mb = (m + 63) >> 6;
    const int rb = blockIdx.y, cb = blockIdx.x;
    if (cb < rb || rb >= mb || cb >= mb) return;
    const int t = threadIdx.x;                   // 0..63

    __shared__ float4 cbox[64];                  // {cz, cw, -cx, -cy}
    __shared__ float  carea[64];
    const int col0 = cb * 64;
    if (col0 + t < m) {
        float4 c = g_sboxes[col0 + t];
        cbox[t]  = make_float4(c.z, c.w, -c.x, -c.y);
        carea[t] = (c.z - c.x) * (c.w - c.y);
    } else {
        cbox[t]  = make_float4(-1e30f, -1e30f, -1e30f, -1e30f);  // -> IoU 0
        carea[t] = 0.f;
    }
    __syncthreads();

    const int row = rb * 64 + t;
    if (row >= m) return;

    const float4 b   = g_sboxes[row];
    const float  bz  = b.z,  bw  = b.w;
    const float  nbx = -b.x, nby = -b.y;
    const float  barea = (b.z - b.x) * (b.w - b.y);

    u64 bits = 0ULL;
    #pragma unroll
    for (int k = 0; k < 64; k++) {
        float4 c  = cbox[k];
        float iw  = fmaxf(fminf(bz, c.x) + fminf(nbx, c.z), 0.f);  // min(x2)-max(x1)
        float ih  = fmaxf(fminf(bw, c.y) + fminf(nby, c.w), 0.f);
        float inter = iw * ih;
        float uni   = (barea + carea[k]) - inter;
        if (fmaf(-0.5f, uni, inter) > 0.f) bits |= (1ULL << k);
    }
    if (cb == rb) bits &= ((~1ULL) << t);        // keep only cols > row
    g_maskT[(size_t)cb * MAXN + row] = bits;     // coalesced across t
}

// ---------------------------------------------------------------------------
// 3) Greedy scan, software-pipelined. 32 warps:
//      warps 0..29 : Phase A issue loads of block b's slice of every future
//                    column j (addresses independent of resolve); Phase B
//                    AND with kept_b + redux.or + OR into remv[j].
//      warp 30     : double-buffered prefetch of next diagonal + nz bitmap
//      warp 31 l0  : serial resolve of block b (visits only conflict rows)
//    Loads never wait on the serial chain; reduce uses redux.sync (2x b32).
// ---------------------------------------------------------------------------
__global__ void scan_kernel(int n) {
    __shared__ u64 remv[NB];
    __shared__ u64 diag[2][64];
    __shared__ u64 nzw[2];
    __shared__ u64 keptw_s;
    const int t = threadIdx.x;
    const int warp = t >> 5, lane = t & 31;
    int m = g_m; if (m > n) m = n;
    const int mb = (m + 63) >> 6;
    if (mb <= 0) return;

    if (t < NB) remv[t] = 0ULL;

    if (warp == 30) {                            // prefetch diag block 0
        u64 d0 = g_maskT[lane];
        u64 d1 = g_maskT[lane + 32];
        diag[0][lane]      = d0;
        diag[0][lane + 32] = d1;
        unsigned b0 = __ballot_sync(0xffffffffu, d0 != 0ULL);
        unsigned b1 = __ballot_sync(0xffffffffu, d1 != 0ULL);
        if (lane == 0) nzw[0] = (u64)b0 | ((u64)b1 << 32);
    }
    __syncthreads();

    u64 p0[MAXJ], p1[MAXJ];

    for (int b = 0; b < mb; b++) {
        const int cur = b & 1;

        if (warp < SWEEP_WARPS) {
            // Phase A: issue loads for block b -> columns j (overlap resolve)
            #pragma unroll
            for (int k = 0; k < MAXJ; k++) {
                const int j = b + 1 + warp + k * SWEEP_WARPS;
                if (j < mb) {
                    const u64* col = g_maskT + (size_t)j * MAXN + b * 64;
                    p0[k] = col[lane];
                    p1[k] = col[lane + 32];
                }
            }
        } else if (warp == 30) {
            const int nb2 = b + 1;
            if (nb2 < mb) {                      // prefetch next diagonal
                const u64* col = g_maskT + (size_t)nb2 * MAXN + nb2 * 64;
                u64 d0 = col[lane], d1 = col[lane + 32];
                diag[cur ^ 1][lane]      = d0;
                diag[cur ^ 1][lane + 32] = d1;
                unsigned b0 = __ballot_sync(0xffffffffu, d0 != 0ULL);
                unsigned b1 = __ballot_sync(0xffffffffu, d1 != 0ULL);
                if (lane == 0) nzw[cur ^ 1] = (u64)b0 | ((u64)b1 << 32);
            }
        } else if (t == 31 * 32) {               // serial resolve
            u64 supp = remv[b];
            const int vr = m - b * 64;
            const u64 valid = (vr >= 64) ? ~0ULL : ((1ULL << vr) - 1ULL);
            u64 rem = nzw[cur] & ~supp & valid;
            while (rem) {
                const int i = __ffsll((long long)rem) - 1;
                rem &= rem - 1ULL;
                if (!((supp >> i) & 1ULL)) {
                    supp |= diag[cur][i];
                    rem  &= ~supp;
                }
            }
            const u64 kept = ~supp & valid;
            keptw_s    = kept;
            g_keepw[b] = kept;
        }
        __syncthreads();

        // Phase B: apply block b's contribution to future remv words
        if (warp < SWEEP_WARPS) {
            const u64 kept = keptw_s;
            const u64 mlo = 0ULL - ((kept >> lane)        & 1ULL);
            const u64 mhi = 0ULL - ((kept >> (lane + 32)) & 1ULL);
            #pragma unroll
            for (int k = 0; k < MAXJ; k++) {
                const int j = b + 1 + warp + k * SWEEP_WARPS;
                if (j < mb) {
                    u64 acc = (p0[k] & mlo) | (p1[k] & mhi);
                    unsigned lo = __reduce_or_sync(0xffffffffu, (unsigned)acc);
                    unsigned hi = __reduce_or_sync(0xffffffffu, (unsigned)(acc >> 32));
                    if (lane == 0) remv[j] |= (u64)lo | ((u64)hi << 32);
                }
            }
        }
        __syncthreads();
    }
}

// ---------------------------------------------------------------------------
// 4) Finalize (original order, coalesced): out[i] = s if (s>=0.6 && kept).
// ---------------------------------------------------------------------------
__global__ void finalize_kernel(const float* __restrict__ scores,
                                float* __restrict__ out, int n) {
    int i = blockIdx.x * blockDim.x + threadIdx.x;
    if (i >= n) return;
    float s = scores[i];
    float v = 0.0f;
    if (s >= 0.6f) {
        int r = g_rank[i];
        if ((g_keepw[r >> 6] >> (r & 63)) & 1ULL) v = s;
    }
    out[i] = v;
}

// ---------------------------------------------------------------------------
extern "C" void kernel_launch(void* const* d_in, const int* in_sizes, int n_in,
                              void* d_out, int out_size) {
    const float* boxes  = (const float*)d_in[0];
    const float* scores = (const float*)d_in[1];
    const int n = in_sizes[1];                 // 6000

    rank_kernel<<<(n * 32 + 255) / 256, 256>>>(boxes, scores, n);

    dim3 grid(NB, NB);
    mask_kernel<<<grid, 64>>>(n);

    scan_kernel<<<1, 1024>>>(n);

    finalize_kernel<<<(n + 255) / 256, 256>>>(scores, (float*)d_out, n);
}

// round 6
// speedup vs baseline: 17.6185x; 1.2127x over previous
#include <cuda_runtime.h>

#define MAXN 6016
#define NB   94      // max number of 64-box blocks
typedef unsigned long long u64;

// Scratch (device globals: allocation is banned; zero-initialized at load)
__device__ float4 g_sboxes[MAXN];
__device__ int    g_rank[MAXN];
__device__ u64    g_maskT[(size_t)NB * MAXN];   // TRANSPOSED: [word][row]
__device__ int    g_m;    // #{scores >= 0.6}; atomicMax (idempotent across replays)

// smem ring: 4 slots x NB columns x 64 rows (u64)  + remv[NB] + keep[NB]
#define SLOT_U64   (NB * 64)
#define SMEM_U64   (4 * SLOT_U64 + 2 * NB)
#define SMEM_BYTES (SMEM_U64 * 8)

__device__ __forceinline__ unsigned smem_u32(const void* p) {
    return (unsigned)__cvta_generic_to_shared(p);
}
__device__ __forceinline__ void cp_async16(unsigned dst, const u64* src) {
    asm volatile("cp.async.cg.shared.global [%0], [%1], 16;" :: "r"(dst), "l"(src));
}
#define CP_COMMIT() asm volatile("cp.async.commit_group;" ::: "memory")
#define CP_WAIT1()  asm volatile("cp.async.wait_group 1;" ::: "memory")

// ---------------------------------------------------------------------------
// 1) Rank of prefix boxes (s >= 0.6). Suffix boxes can neither appear in the
//    output nor suppress a prefix box, so their warps exit. Prefix ranks are
//    exactly 0..m-1; m published via idempotent atomicMax.
// ---------------------------------------------------------------------------
__global__ void rank_kernel(const float* __restrict__ boxes,
                            const float* __restrict__ scores, int n) {
    int gw   = (blockIdx.x * blockDim.x + threadIdx.x) >> 5;
    int lane = threadIdx.x & 31;
    if (gw >= n) return;
    float s = scores[gw];
    if (s < 0.6f) return;
    int cnt = 0;
    for (int j = lane; j < n; j += 32) {
        float sj = scores[j];
        cnt += (int)((sj > s) | ((sj == s) & (j < gw)));
    }
    #pragma unroll
    for (int o = 16; o; o >>= 1) cnt += __shfl_down_sync(0xffffffffu, cnt, o);
    if (lane == 0) {
        const float4* b4 = (const float4*)boxes;
        g_sboxes[cnt] = b4[gw];
        g_rank[gw]    = cnt;
        atomicMax(&g_m, cnt + 1);
    }
}

// ---------------------------------------------------------------------------
// 2) Suppression mask on the prefix, TRANSPOSED: g_maskT[cb][row].
//    Division-free exact threshold: iou>0.5 <=> fma(-0.5,uni,inter)>0.
// ---------------------------------------------------------------------------
__global__ void mask_kernel(int n) {
    int m = g_m; if (m > n) m = n;
    const int mb = (m + 63) >> 6;
    const int rb = blockIdx.y, cb = blockIdx.x;
    if (cb < rb || rb >= mb || cb >= mb) return;
    const int t = threadIdx.x;                   // 0..63

    __shared__ float4 cbox[64];                  // {cz, cw, -cx, -cy}
    __shared__ float  carea[64];
    const int col0 = cb * 64;
    if (col0 + t < m) {
        float4 c = g_sboxes[col0 + t];
        cbox[t]  = make_float4(c.z, c.w, -c.x, -c.y);
        carea[t] = (c.z - c.x) * (c.w - c.y);
    } else {
        cbox[t]  = make_float4(-1e30f, -1e30f, -1e30f, -1e30f);  // -> IoU 0
        carea[t] = 0.f;
    }
    __syncthreads();

    const int row = rb * 64 + t;
    if (row >= m) return;

    const float4 b   = g_sboxes[row];
    const float  bz  = b.z,  bw  = b.w;
    const float  nbx = -b.x, nby = -b.y;
    const float  barea = (b.z - b.x) * (b.w - b.y);

    u64 bits = 0ULL;
    #pragma unroll
    for (int k = 0; k < 64; k++) {
        float4 c  = cbox[k];
        float iw  = fmaxf(fminf(bz, c.x) + fminf(nbx, c.z), 0.f);
        float ih  = fmaxf(fminf(bw, c.y) + fminf(nby, c.w), 0.f);
        float inter = iw * ih;
        float uni   = (barea + carea[k]) - inter;
        if (fmaf(-0.5f, uni, inter) > 0.f) bits |= (1ULL << k);
    }
    if (cb == rb) bits &= ((~1ULL) << t);        // keep only cols > row
    g_maskT[(size_t)cb * MAXN + row] = bits;
}

// ---------------------------------------------------------------------------
// 3) Greedy scan + finalize, one CTA / 32 warps, ONE barrier per block:
//    warp 31: resolve(b) from smem slice; inline contribution of block b to
//             column b+1 (shfl kept + redux.or + atomicOr) -> next resolve
//             never waits on the sweep warps.
//    warps 0..30: cp.async-issue block b+2's column slices into 4-slot smem
//             ring; lagged sweep of block b-1 into cols >= b+1 from smem.
// ---------------------------------------------------------------------------
__global__ void scan_kernel(const float* __restrict__ scores,
                            float* __restrict__ out, int n) {
    extern __shared__ u64 sbuf[];
    u64* remv = sbuf + 4 * SLOT_U64;
    u64* keep = remv + NB;
    const int t = threadIdx.x;
    const int warp = t >> 5, lane = t & 31;
    int m = g_m; if (m > n) m = n;
    const int mb = (m + 63) >> 6;

    if (t < NB) { remv[t] = 0ULL; keep[t] = 0ULL; }
    __syncthreads();

    // Priming: blocks 0 and 1 into slots 0,1 (cols >= X)
    if (warp < 31) {
        #pragma unroll
        for (int X = 0; X <= 1; X++) {
            if (X < mb) {
                for (int j = X + warp; j < mb; j += 31) {
                    u64* dst = sbuf + (size_t)(X & 3) * SLOT_U64 + j * 64 + 2 * lane;
                    cp_async16(smem_u32(dst),
                               g_maskT + (size_t)j * MAXN + X * 64 + 2 * lane);
                }
            }
            CP_COMMIT();
        }
        CP_WAIT1();
    }
    __syncthreads();

    for (int b = 0; b < mb; b++) {
        if (warp == 31) {
            const u64* dcol = sbuf + (size_t)(b & 3) * SLOT_U64 + b * 64;
            u64 d0 = dcol[2 * lane], d1 = dcol[2 * lane + 1];
            u64 nzme = ((u64)(d0 != 0ULL) << (2 * lane))
                     | ((u64)(d1 != 0ULL) << (2 * lane + 1));
            unsigned nlo = __reduce_or_sync(0xffffffffu, (unsigned)nzme);
            unsigned nhi = __reduce_or_sync(0xffffffffu, (unsigned)(nzme >> 32));
            u64 kept = 0ULL;
            if (lane == 0) {
                u64 supp = remv[b];
                const int vr = m - b * 64;
                const u64 valid = (vr >= 64) ? ~0ULL : ((1ULL << vr) - 1ULL);
                u64 rem = ((u64)nlo | ((u64)nhi << 32)) & ~supp & valid;
                while (rem) {
                    const int i = __ffsll((long long)rem) - 1;
                    rem &= rem - 1ULL;
                    if (!((supp >> i) & 1ULL)) {
                        supp |= dcol[i];
                        rem  &= ~supp;
                    }
                }
                kept = ~supp & valid;
                keep[b] = kept;
            }
            kept = __shfl_sync(0xffffffffu, kept, 0);
            if (b + 1 < mb) {  // inline: block b's contribution to column b+1
                const u64* ccol = sbuf + (size_t)(b & 3) * SLOT_U64 + (b + 1) * 64;
                u64 a0 = ccol[2 * lane]     & (0ULL - ((kept >> (2 * lane))     & 1ULL));
                u64 a1 = ccol[2 * lane + 1] & (0ULL - ((kept >> (2 * lane + 1)) & 1ULL));
                u64 acc = a0 | a1;
                unsigned lo = __reduce_or_sync(0xffffffffu, (unsigned)acc);
                unsigned hi = __reduce_or_sync(0xffffffffu, (unsigned)(acc >> 32));
                if (lane == 0) atomicOr(&remv[b + 1], (u64)lo | ((u64)hi << 32));
            }
        } else {
            // issue block b+2 slices into slot (b+2)&3
            const int X = b + 2;
            if (X < mb) {
                for (int j = X + warp; j < mb; j += 31) {
                    u64* dst = sbuf + (size_t)(X & 3) * SLOT_U64 + j * 64 + 2 * lane;
                    cp_async16(smem_u32(dst),
                               g_maskT + (size_t)j * MAXN + X * 64 + 2 * lane);
                }
            }
            CP_COMMIT();
            // lagged sweep: block b-1 -> columns >= b+1 (smem-resident)
            if (b >= 1) {
                const u64 kp = keep[b - 1];
                const u64 m0 = 0ULL - ((kp >> (2 * lane))     & 1ULL);
                const u64 m1 = 0ULL - ((kp >> (2 * lane + 1)) & 1ULL);
                const u64* s = sbuf + (size_t)((b - 1) & 3) * SLOT_U64;
                for (int j = b + 1 + warp; j < mb; j += 31) {
                    u64 acc = (s[j * 64 + 2 * lane] & m0)
                            | (s[j * 64 + 2 * lane + 1] & m1);
                    unsigned lo = __reduce_or_sync(0xffffffffu, (unsigned)acc);
                    unsigned hi = __reduce_or_sync(0xffffffffu, (unsigned)(acc >> 32));
                    if (lane == 0) atomicOr(&remv[j], (u64)lo | ((u64)hi << 32));
                }
            }
            CP_WAIT1();   // slot for block b+1 complete before next iteration
        }
        __syncthreads();
    }

    // Fused finalize: out[i] = s if (s >= 0.6 && kept) else 0
    for (int i = t; i < n; i += 1024) {
        float s = scores[i];
        float v = 0.0f;
        if (s >= 0.6f) {
            int r = g_rank[i];
            if ((keep[r >> 6] >> (r & 63)) & 1ULL) v = s;
        }
        out[i] = v;
    }
}

// ---------------------------------------------------------------------------
extern "C" void kernel_launch(void* const* d_in, const int* in_sizes, int n_in,
                              void* d_out, int out_size) {
    const float* boxes  = (const float*)d_in[0];
    const float* scores = (const float*)d_in[1];
    const int n = in_sizes[1];                 // 6000

    cudaFuncSetAttribute(scan_kernel,
                         cudaFuncAttributeMaxDynamicSharedMemorySize, SMEM_BYTES);

    rank_kernel<<<(n * 32 + 255) / 256, 256>>>(boxes, scores, n);

    dim3 grid(NB, NB);
    mask_kernel<<<grid, 64>>>(n);

    scan_kernel<<<1, 1024, SMEM_BYTES>>>(scores, (float*)d_out, n);
}